// round 5
// baseline (speedup 1.0000x reference)
#include <cuda_runtime.h>
#include <cstdint>

// BFP quantize/dequantize: blocks of 16 contiguous fp32 share exponent
// e = floor(log2(max|x|)); q = clip(rint(x * 2^(7-e)), -128, 127); out = q * 2^(e-7).
//
// Layout: 4 consecutive lanes hold one 16-elem BFP block as float4s ->
// every warp LDG.128 covers a contiguous 512 B. Block max via 2 butterfly
// shuffles in the 4-lane group. 4 independent float4 loads in flight per
// thread (MLP_p1 = 4), streaming cache hints (touch-once data).

__device__ __forceinline__ float4 bfp_qdq_vec(float4 v)
{
    float m = fmaxf(fmaxf(fabsf(v.x), fabsf(v.y)),
                    fmaxf(fabsf(v.z), fabsf(v.w)));
    m = fmaxf(m, __shfl_xor_sync(0xFFFFFFFFu, m, 1));
    m = fmaxf(m, __shfl_xor_sync(0xFFFFFFFFu, m, 2));

    float4 o;
    if (m > 0.0f) {
        // biased exponent of block max; floor(log2(m)) = eb - 127 for normals
        unsigned eb = __float_as_uint(m) >> 23;
        eb = eb < 8u ? 8u : eb;   // keep bit-built scales finite (denormal max)
        float scale = __uint_as_float((eb - 7u) << 23);   // 2^(e-7)
        float inv   = __uint_as_float((261u - eb) << 23); // 2^(7-e)

        o.x = fminf(127.0f, fmaxf(-128.0f, rintf(v.x * inv))) * scale;
        o.y = fminf(127.0f, fmaxf(-128.0f, rintf(v.y * inv))) * scale;
        o.z = fminf(127.0f, fmaxf(-128.0f, rintf(v.z * inv))) * scale;
        o.w = fminf(127.0f, fmaxf(-128.0f, rintf(v.w * inv))) * scale;
    } else {
        o.x = 0.0f; o.y = 0.0f; o.z = 0.0f; o.w = 0.0f;
    }
    return o;
}

__global__ void __launch_bounds__(512) bfp_qdq_kernel(
    const float4* __restrict__ in, float4* __restrict__ out, int n4)
{
    const int stride = gridDim.x * blockDim.x;
    const int base = blockIdx.x * blockDim.x + threadIdx.x;

    int i0 = base;
    int i1 = base + stride;
    int i2 = base + 2 * stride;
    int i3 = base + 3 * stride;

    if (i3 < n4) {
        // fast path (exact for the bench shape): 4 loads front-batched, MLP=4
        float4 v0 = __ldcs(&in[i0]);
        float4 v1 = __ldcs(&in[i1]);
        float4 v2 = __ldcs(&in[i2]);
        float4 v3 = __ldcs(&in[i3]);
        float4 o0 = bfp_qdq_vec(v0);
        float4 o1 = bfp_qdq_vec(v1);
        float4 o2 = bfp_qdq_vec(v2);
        float4 o3 = bfp_qdq_vec(v3);
        __stcs(&out[i0], o0);
        __stcs(&out[i1], o1);
        __stcs(&out[i2], o2);
        __stcs(&out[i3], o3);
    } else {
        // generic tail (dead at the bench shape)
        #pragma unroll
        for (int k = 0; k < 4; k++) {
            int i = base + k * stride;
            if (i < n4) __stcs(&out[i], bfp_qdq_vec(__ldcs(&in[i])));
        }
    }
}

extern "C" void kernel_launch(void* const* d_in, const int* in_sizes, int n_in,
                              void* d_out, int out_size)
{
    const float4* in  = (const float4*)d_in[0];
    float4*       out = (float4*)d_out;
    int n  = in_sizes[0];          // 134,217,728
    int n4 = n >> 2;               // 33,554,432 float4s

    const int threads = 512;
    const int per_cta = threads * 4;               // 4 float4s per thread
    int blocks = (n4 + per_cta - 1) / per_cta;     // 16,384 CTAs (exact)
    bfp_qdq_kernel<<<blocks, threads>>>(in, out, n4);
}

// round 7
// speedup vs baseline: 1.0048x; 1.0048x over previous
#include <cuda_runtime.h>
#include <cstdint>

// BFP quantize/dequantize: blocks of 16 contiguous fp32 share exponent
// e = floor(log2(max|x|)); q = clip(rint(x * 2^(7-e)), -128, 127); out = q * 2^(e-7).
//
// Config = R3 (best known: 256 thr, MLP=2, 24 regs, occ 80%) + streaming
// cache hints (touch-once data). 4 consecutive lanes hold one 16-elem BFP
// block as float4s -> every warp LDG.128 covers a contiguous 512 B.
// Block max via 2 butterfly shuffles in the 4-lane group.

__device__ __forceinline__ float4 bfp_qdq_vec(float4 v)
{
    float m = fmaxf(fmaxf(fabsf(v.x), fabsf(v.y)),
                    fmaxf(fabsf(v.z), fabsf(v.w)));
    m = fmaxf(m, __shfl_xor_sync(0xFFFFFFFFu, m, 1));
    m = fmaxf(m, __shfl_xor_sync(0xFFFFFFFFu, m, 2));

    float4 o;
    if (m > 0.0f) {
        // biased exponent of block max; floor(log2(m)) = eb - 127 for normals
        unsigned eb = __float_as_uint(m) >> 23;
        eb = eb < 8u ? 8u : eb;   // keep bit-built scales finite (denormal max)
        float scale = __uint_as_float((eb - 7u) << 23);   // 2^(e-7)
        float inv   = __uint_as_float((261u - eb) << 23); // 2^(7-e)

        o.x = fminf(127.0f, fmaxf(-128.0f, rintf(v.x * inv))) * scale;
        o.y = fminf(127.0f, fmaxf(-128.0f, rintf(v.y * inv))) * scale;
        o.z = fminf(127.0f, fmaxf(-128.0f, rintf(v.z * inv))) * scale;
        o.w = fminf(127.0f, fmaxf(-128.0f, rintf(v.w * inv))) * scale;
    } else {
        o.x = 0.0f; o.y = 0.0f; o.z = 0.0f; o.w = 0.0f;
    }
    return o;
}

__global__ void __launch_bounds__(256) bfp_qdq_kernel(
    const float4* __restrict__ in, float4* __restrict__ out, int n4)
{
    const int stride = gridDim.x * blockDim.x;
    const int i0 = blockIdx.x * blockDim.x + threadIdx.x;
    const int i1 = i0 + stride;

    if (i1 < n4) {
        // fast path (exact for the bench shape): 2 loads front-batched, MLP=2
        float4 v0 = __ldcs(&in[i0]);
        float4 v1 = __ldcs(&in[i1]);
        float4 o0 = bfp_qdq_vec(v0);
        float4 o1 = bfp_qdq_vec(v1);
        __stcs(&out[i0], o0);
        __stcs(&out[i1], o1);
    } else if (i0 < n4) {
        __stcs(&out[i0], bfp_qdq_vec(__ldcs(&in[i0])));
    }
}

extern "C" void kernel_launch(void* const* d_in, const int* in_sizes, int n_in,
                              void* d_out, int out_size)
{
    const float4* in  = (const float4*)d_in[0];
    float4*       out = (float4*)d_out;
    int n  = in_sizes[0];          // 134,217,728
    int n4 = n >> 2;               // 33,554,432 float4s

    const int threads = 256;
    const int per_cta = threads * 2;               // 2 float4s per thread
    int blocks = (n4 + per_cta - 1) / per_cta;     // 65,536 CTAs (exact)
    bfp_qdq_kernel<<<blocks, threads>>>(in, out, n4);
}